// round 6
// baseline (speedup 1.0000x reference)
#include <cuda_runtime.h>
#include <cuda_fp16.h>

typedef unsigned int u32;

#define B_    2
#define N_    512
#define F_    128
#define Z_    256
#define MID_  128
#define ICH   8           // i-chunks
#define TI    64          // N_/ICH, i per chunk
#define TJ    32          // j rows per CTA in edge kernel
#define PADH  136         // half-padding for A smem rows (conflict-free)

// ---------------- device scratch (no allocation allowed) ----------------
__device__ float  g_base   [B_*N_*MID_];       // z@W1 + b1 + msg_g
__device__ float  g_addv   [B_*N_*MID_];       // z@W2 + b2 + be
__device__ float  g_h1     [B_*N_*MID_];       // z@Wo1 + bo1
__device__ float  g_msgg   [B_*MID_];
__device__ __half g_WeTh   [MID_*F_];          // transposed We, [n][k], fp16
__device__ float  g_partial[(size_t)B_*ICH*N_*MID_];   // 4 MB partial maxes

// ---------------- prep: msg_g and We transpose/convert ----------------
__global__ void prep_kernel(const float* __restrict__ graph_fts,
                            const float* __restrict__ Wg,
                            const float* __restrict__ bg,
                            const float* __restrict__ We) {
    int tid = threadIdx.x;
    if (tid < 256) {
        int b = tid >> 7, f = tid & 127;
        float acc = bg[f];
        #pragma unroll 8
        for (int k = 0; k < F_; k++) acc += graph_fts[b*F_ + k] * Wg[k*MID_ + f];
        g_msgg[b*MID_ + f] = acc;
    }
    for (int m = tid; m < MID_*F_; m += blockDim.x) {
        int n = m >> 7, k = m & 127;
        g_WeTh[n*F_ + k] = __float2half(We[k*MID_ + n]);
    }
}

// ---------------- stage A: three z-GEMMs in fp32 ----------------
// grid (3, 32, 2): ws, n-tile(16 rows), b.  block 256.
__global__ __launch_bounds__(256) void stageA_kernel(
    const float* __restrict__ node, const float* __restrict__ hidden,
    const float* __restrict__ W1, const float* __restrict__ b1,
    const float* __restrict__ W2, const float* __restrict__ b2,
    const float* __restrict__ Wo1, const float* __restrict__ bo1,
    const float* __restrict__ be) {
    int ws = blockIdx.x, nt = blockIdx.y, b = blockIdx.z;
    const float* W    = (ws == 0) ? W1  : (ws == 1) ? W2  : Wo1;
    const float* bias = (ws == 0) ? b1  : (ws == 1) ? b2  : bo1;
    float*       outp = (ws == 0) ? g_base : (ws == 1) ? g_addv : g_h1;

    __shared__ float zs [16*Z_];     // 16 KB
    __shared__ float Wts[64*MID_];   // 32 KB
    int tid = threadIdx.x;
    int nbase = nt * 16;

    // load z tile (concat node/hidden)
    for (int m = tid; m < 16*Z_/4; m += 256) {
        int r = m >> 6, col = (m & 63) * 4;
        const float* src = (col < F_)
            ? (node   + ((size_t)b*N_ + nbase + r)*F_ + col)
            : (hidden + ((size_t)b*N_ + nbase + r)*F_ + (col - F_));
        *(float4*)&zs[r*Z_ + col] = *(const float4*)src;
    }

    float acc[8];
    #pragma unroll
    for (int c = 0; c < 8; c++) acc[c] = 0.f;
    int r  = tid >> 4;
    int c0 = (tid & 15) * 8;

    for (int kc = 0; kc < 4; kc++) {
        __syncthreads();
        for (int m = tid; m < 64*MID_/4; m += 256) {
            int rr = m >> 5, cg = (m & 31) * 4;
            *(float4*)&Wts[rr*MID_ + cg] = *(const float4*)&W[(size_t)(kc*64 + rr)*MID_ + cg];
        }
        __syncthreads();
        #pragma unroll 16
        for (int k = 0; k < 64; k++) {
            float a = zs[r*Z_ + kc*64 + k];
            float4 w0 = *(const float4*)&Wts[k*MID_ + c0];
            float4 w1 = *(const float4*)&Wts[k*MID_ + c0 + 4];
            acc[0] += a*w0.x; acc[1] += a*w0.y; acc[2] += a*w0.z; acc[3] += a*w0.w;
            acc[4] += a*w1.x; acc[5] += a*w1.y; acc[6] += a*w1.z; acc[7] += a*w1.w;
        }
    }

    #pragma unroll
    for (int c = 0; c < 8; c++) {
        float extra = bias[c0 + c];
        if (ws == 0) extra += g_msgg[b*MID_ + c0 + c];
        else if (ws == 1) extra += be[c0 + c];
        outp[((size_t)b*N_ + nbase + r)*MID_ + c0 + c] = acc[c] + extra;
    }
}

// ---------------- the big one: edge GEMM + masked running max ----------------
__device__ __forceinline__ void mma16816(float d[4], const u32 a[4], const u32 b[2]) {
    asm volatile(
        "mma.sync.aligned.m16n8k16.row.col.f32.f16.f16.f32 "
        "{%0,%1,%2,%3}, {%4,%5,%6,%7}, {%8,%9}, {%0,%1,%2,%3};\n"
        : "+f"(d[0]), "+f"(d[1]), "+f"(d[2]), "+f"(d[3])
        : "r"(a[0]), "r"(a[1]), "r"(a[2]), "r"(a[3]), "r"(b[0]), "r"(b[1]));
}

// store a TJ x 128 fp32 slab (held as 4 float4/thread) into fp16 smem buffer
__device__ __forceinline__ void store_slab(__half* As, int tid, const float4 pf[4]) {
    #pragma unroll
    for (int l = 0; l < 4; l++) {
        int m = l*256 + tid, row = m >> 5, c4 = (m & 31) * 4;
        __half2 h0 = __floats2half2_rn(pf[l].x, pf[l].y);
        __half2 h1 = __floats2half2_rn(pf[l].z, pf[l].w);
        uint2 u;
        u.x = *(u32*)&h0;
        u.y = *(u32*)&h1;
        *(uint2*)&As[row*PADH + c4] = u;   // single 8B store, conflict-free
    }
}

// grid (ICH, N_/TJ, B_) = (8, 16, 2) = 256 CTAs, one wave at 2 CTA/SM.
// block 256 = 8 warps; warp w covers all 32 j-rows x 16 n-cols (ncol = w*16).
__global__ __launch_bounds__(256, 2) void edge_kernel(
    const float* __restrict__ edge, const float* __restrict__ adj) {
    __shared__ __align__(16) unsigned char smraw[2*TJ*PADH*2];  // 17408 B
    __half* Asbuf = (__half*)smraw;      // two buffers of TJ*PADH halves
    float*  stage = (float*)smraw;       // [TJ][MID_] f32 staging (after loop)

    int ic = blockIdx.x, jt = blockIdx.y, b = blockIdx.z;
    int jbase = jt * TJ, ibase = ic * TI;
    int tid = threadIdx.x, w = tid >> 5, lane = tid & 31;
    int g = lane >> 2, t = lane & 3;
    int ncol = w * 16;

    // persistent B fragments (We), loaded once from global: 32 regs
    u32 Bf[8][2][2];
    #pragma unroll
    for (int ks = 0; ks < 8; ks++)
        #pragma unroll
        for (int nf = 0; nf < 2; nf++) {
            int n0 = ncol + nf*8 + g;
            int kb = ks*16 + 2*t;
            Bf[ks][nf][0] = *(const u32*)&g_WeTh[n0*F_ + kb];
            Bf[ks][nf][1] = *(const u32*)&g_WeTh[n0*F_ + kb + 8];
        }

    float maxacc[2][2][4];
    #pragma unroll
    for (int mf = 0; mf < 2; mf++)
        #pragma unroll
        for (int nf = 0; nf < 2; nf++)
            #pragma unroll
            for (int e = 0; e < 4; e++) maxacc[mf][nf][e] = -1e30f;

    // initial slab (i = ibase) + its addv/adj
    float4 pf[4];
    {
        const float4* eb = (const float4*)(edge + (((size_t)b*N_ + ibase)*N_ + jbase)*F_);
        #pragma unroll
        for (int l = 0; l < 4; l++) pf[l] = eb[l*256 + tid];
    }
    float avn[2][2], adjn[2][2];
    {
        const float* avp = g_addv + ((size_t)b*N_ + ibase)*MID_;
        #pragma unroll
        for (int nf = 0; nf < 2; nf++) {
            avn[nf][0] = avp[ncol + nf*8 + 2*t];
            avn[nf][1] = avp[ncol + nf*8 + 2*t + 1];
        }
        const float* ap = adj + ((size_t)b*N_ + ibase)*N_ + jbase;
        #pragma unroll
        for (int mf = 0; mf < 2; mf++) {
            adjn[mf][0] = ap[mf*16 + g];
            adjn[mf][1] = ap[mf*16 + g + 8];
        }
    }
    store_slab(Asbuf, tid, pf);
    __syncthreads();

    int cur = 0;
    #pragma unroll 1
    for (int it = 0; it < TI; it++) {
        float avc[2][2], adjc[2][2];
        #pragma unroll
        for (int nf = 0; nf < 2; nf++) { avc[nf][0] = avn[nf][0]; avc[nf][1] = avn[nf][1]; }
        #pragma unroll
        for (int mf = 0; mf < 2; mf++) { adjc[mf][0] = adjn[mf][0]; adjc[mf][1] = adjn[mf][1]; }

        bool more = (it + 1 < TI);
        if (more) {   // prefetch next slab + next addv/adj into registers (hidden under MMA)
            int ni = ibase + it + 1;
            const float4* eb = (const float4*)(edge + (((size_t)b*N_ + ni)*N_ + jbase)*F_);
            #pragma unroll
            for (int l = 0; l < 4; l++) pf[l] = eb[l*256 + tid];
            const float* avp = g_addv + ((size_t)b*N_ + ni)*MID_;
            #pragma unroll
            for (int nf = 0; nf < 2; nf++) {
                avn[nf][0] = avp[ncol + nf*8 + 2*t];
                avn[nf][1] = avp[ncol + nf*8 + 2*t + 1];
            }
            const float* ap = adj + ((size_t)b*N_ + ni)*N_ + jbase;
            #pragma unroll
            for (int mf = 0; mf < 2; mf++) {
                adjn[mf][0] = ap[mf*16 + g];
                adjn[mf][1] = ap[mf*16 + g + 8];
            }
        }

        // acc init = addv (folds broadcast add into MMA accumulator)
        float d[2][2][4];
        #pragma unroll
        for (int mf = 0; mf < 2; mf++)
            #pragma unroll
            for (int nf = 0; nf < 2; nf++) {
                d[mf][nf][0] = avc[nf][0]; d[mf][nf][1] = avc[nf][1];
                d[mf][nf][2] = avc[nf][0]; d[mf][nf][3] = avc[nf][1];
            }

        const __half* As = Asbuf + cur * (TJ*PADH);
        #pragma unroll
        for (int ks = 0; ks < 8; ks++) {
            u32 a[2][4];
            #pragma unroll
            for (int mf = 0; mf < 2; mf++) {
                const __half* ap = As + (mf*16 + g)*PADH + ks*16 + 2*t;
                a[mf][0] = *(const u32*)(ap);
                a[mf][1] = *(const u32*)(ap + 8*PADH);
                a[mf][2] = *(const u32*)(ap + 8);
                a[mf][3] = *(const u32*)(ap + 8*PADH + 8);
            }
            #pragma unroll
            for (int nf = 0; nf < 2; nf++)
                #pragma unroll
                for (int mf = 0; mf < 2; mf++)
                    mma16816(d[mf][nf], a[mf], Bf[ks][nf]);
        }

        // masked running max over i
        #pragma unroll
        for (int mf = 0; mf < 2; mf++) {
            bool p0 = adjc[mf][0] > 0.f;
            bool p1 = adjc[mf][1] > 0.f;
            #pragma unroll
            for (int nf = 0; nf < 2; nf++) {
                if (p0) {
                    maxacc[mf][nf][0] = fmaxf(maxacc[mf][nf][0], d[mf][nf][0]);
                    maxacc[mf][nf][1] = fmaxf(maxacc[mf][nf][1], d[mf][nf][1]);
                }
                if (p1) {
                    maxacc[mf][nf][2] = fmaxf(maxacc[mf][nf][2], d[mf][nf][2]);
                    maxacc[mf][nf][3] = fmaxf(maxacc[mf][nf][3], d[mf][nf][3]);
                }
            }
        }

        // double-buffer: write NEXT slab into the other buffer, single sync
        if (more) store_slab(Asbuf + (cur^1) * (TJ*PADH), tid, pf);
        __syncthreads();
        cur ^= 1;
    }

    // stage maxacc in smem (aliases As — all reads done), then coalesced store
    #pragma unroll
    for (int mf = 0; mf < 2; mf++)
        #pragma unroll
        for (int nf = 0; nf < 2; nf++)
            #pragma unroll
            for (int e = 0; e < 4; e++) {
                int jl = mf*16 + g + (e >> 1)*8;
                int n  = ncol + nf*8 + 2*t + (e & 1);
                stage[jl*MID_ + n] = maxacc[mf][nf][e];
            }
    __syncthreads();
    float4* outp = (float4*)(g_partial + (((size_t)b*ICH + ic)*N_ + jbase)*MID_);
    const float4* st4 = (const float4*)stage;
    #pragma unroll
    for (int l = 0; l < 4; l++) outp[l*256 + tid] = st4[l*256 + tid];
}

// ---------------- combine: chunk-max + base, then @Wo2 + bo2 + h1, relu ----------------
// grid 128 (jt 0..63, b 0..1), block 256, 8 j-rows per CTA.
__global__ __launch_bounds__(256) void combine_kernel(
    const float* __restrict__ Wo2, const float* __restrict__ bo2,
    float* __restrict__ out) {
    int jt = blockIdx.x & 63, b = blockIdx.x >> 6;
    int jbase = jt * 8;
    __shared__ float reds[8*MID_];    // 4 KB
    __shared__ float Wts[32*MID_];    // 16 KB
    int tid = threadIdx.x;
    int r = tid >> 5, c0 = (tid & 31) * 4;

    float4 mx = make_float4(-1e30f, -1e30f, -1e30f, -1e30f);
    #pragma unroll
    for (int icc = 0; icc < ICH; icc++) {   // fully unrolled: 8 independent loads in flight
        float4 v = *(const float4*)&g_partial[(((size_t)b*ICH + icc)*N_ + jbase + r)*MID_ + c0];
        mx.x = fmaxf(mx.x, v.x); mx.y = fmaxf(mx.y, v.y);
        mx.z = fmaxf(mx.z, v.z); mx.w = fmaxf(mx.w, v.w);
    }
    float4 bs = *(const float4*)&g_base[((size_t)b*N_ + jbase + r)*MID_ + c0];
    mx.x += bs.x; mx.y += bs.y; mx.z += bs.z; mx.w += bs.w;
    *(float4*)&reds[r*MID_ + c0] = mx;

    float4 acc = make_float4(0.f, 0.f, 0.f, 0.f);
    for (int kc = 0; kc < 4; kc++) {
        __syncthreads();
        for (int m = tid; m < 32*MID_/4; m += 256) {
            int rr = m >> 5, cg = (m & 31) * 4;
            *(float4*)&Wts[rr*MID_ + cg] = *(const float4*)&Wo2[(size_t)(kc*32 + rr)*MID_ + cg];
        }
        __syncthreads();
        #pragma unroll 8
        for (int k = 0; k < 32; k++) {
            float a = reds[r*MID_ + kc*32 + k];
            float4 wv = *(const float4*)&Wts[k*MID_ + c0];
            acc.x += a*wv.x; acc.y += a*wv.y; acc.z += a*wv.z; acc.w += a*wv.w;
        }
    }

    float4 bo = *(const float4*)&bo2[c0];
    float4 h1 = *(const float4*)&g_h1[((size_t)b*N_ + jbase + r)*MID_ + c0];
    float4 o;
    o.x = fmaxf(acc.x + bo.x + h1.x, 0.f);
    o.y = fmaxf(acc.y + bo.y + h1.y, 0.f);
    o.z = fmaxf(acc.z + bo.z + h1.z, 0.f);
    o.w = fmaxf(acc.w + bo.w + h1.w, 0.f);
    *(float4*)&out[((size_t)b*N_ + jbase + r)*MID_ + c0] = o;
}

// ---------------- launch ----------------
extern "C" void kernel_launch(void* const* d_in, const int* in_sizes, int n_in,
                              void* d_out, int out_size) {
    const float* node   = (const float*)d_in[0];
    const float* edge   = (const float*)d_in[1];
    const float* graph  = (const float*)d_in[2];
    const float* adj    = (const float*)d_in[3];
    const float* hidden = (const float*)d_in[4];
    const float* W1  = (const float*)d_in[5];
    const float* b1  = (const float*)d_in[6];
    const float* W2  = (const float*)d_in[7];
    const float* b2  = (const float*)d_in[8];
    const float* We  = (const float*)d_in[9];
    const float* be  = (const float*)d_in[10];
    const float* Wg  = (const float*)d_in[11];
    const float* bg  = (const float*)d_in[12];
    const float* Wo1 = (const float*)d_in[13];
    const float* bo1 = (const float*)d_in[14];
    const float* Wo2 = (const float*)d_in[15];
    const float* bo2 = (const float*)d_in[16];

    prep_kernel<<<1, 256>>>(graph, Wg, bg, We);
    stageA_kernel<<<dim3(3, 32, 2), 256>>>(node, hidden, W1, b1, W2, b2, Wo1, bo1, be);
    edge_kernel<<<dim3(ICH, N_/TJ, B_), 256>>>(edge, adj);
    combine_kernel<<<128, 256>>>(Wo2, bo2, (float*)d_out);
}

// round 8
// speedup vs baseline: 1.3989x; 1.3989x over previous
#include <cuda_runtime.h>
#include <cuda_fp16.h>

typedef unsigned int u32;

#define B_    2
#define N_    512
#define F_    128
#define Z_    256
#define MID_  128
#define ICH   32          // i-chunks
#define TI    16          // i per chunk
#define TJ    64          // j rows per CTA in edge kernel
#define PADH  136         // half-padding for A smem rows (conflict-free, LDSM-safe)

// ---------------- device scratch (no allocation allowed) ----------------
__device__ float  g_base   [B_*N_*MID_];       // z@W1 + b1 + msg_g
__device__ float  g_addv   [B_*N_*MID_];       // z@W2 + b2 + be
__device__ float  g_h1     [B_*N_*MID_];       // z@Wo1 + bo1
__device__ float  g_msgg   [B_*MID_];
__device__ __half g_WeTh   [MID_*F_];          // transposed We, [n][k], fp16
__device__ float  g_partial[(size_t)B_*ICH*N_*MID_];   // 16 MB partial maxes

// ---------------- prep: msg_g and We transpose/convert ----------------
__global__ void prep_kernel(const float* __restrict__ graph_fts,
                            const float* __restrict__ Wg,
                            const float* __restrict__ bg,
                            const float* __restrict__ We) {
    int tid = threadIdx.x;
    if (tid < 256) {
        int b = tid >> 7, f = tid & 127;
        float acc = bg[f];
        #pragma unroll 8
        for (int k = 0; k < F_; k++) acc += graph_fts[b*F_ + k] * Wg[k*MID_ + f];
        g_msgg[b*MID_ + f] = acc;
    }
    for (int m = tid; m < MID_*F_; m += blockDim.x) {
        int n = m >> 7, k = m & 127;
        g_WeTh[n*F_ + k] = __float2half(We[k*MID_ + n]);
    }
}

// ---------------- stage A: three z-GEMMs in fp32 ----------------
// grid (3, 32, 2): ws, n-tile(16 rows), b.  block 256.
__global__ __launch_bounds__(256) void stageA_kernel(
    const float* __restrict__ node, const float* __restrict__ hidden,
    const float* __restrict__ W1, const float* __restrict__ b1,
    const float* __restrict__ W2, const float* __restrict__ b2,
    const float* __restrict__ Wo1, const float* __restrict__ bo1,
    const float* __restrict__ be) {
    int ws = blockIdx.x, nt = blockIdx.y, b = blockIdx.z;
    const float* W    = (ws == 0) ? W1  : (ws == 1) ? W2  : Wo1;
    const float* bias = (ws == 0) ? b1  : (ws == 1) ? b2  : bo1;
    float*       outp = (ws == 0) ? g_base : (ws == 1) ? g_addv : g_h1;

    __shared__ float zs [16*Z_];
    __shared__ float Wts[64*MID_];
    int tid = threadIdx.x;
    int nbase = nt * 16;

    for (int m = tid; m < 16*Z_/4; m += 256) {
        int r = m >> 6, col = (m & 63) * 4;
        const float* src = (col < F_)
            ? (node   + ((size_t)b*N_ + nbase + r)*F_ + col)
            : (hidden + ((size_t)b*N_ + nbase + r)*F_ + (col - F_));
        *(float4*)&zs[r*Z_ + col] = *(const float4*)src;
    }

    float acc[8];
    #pragma unroll
    for (int c = 0; c < 8; c++) acc[c] = 0.f;
    int r  = tid >> 4;
    int c0 = (tid & 15) * 8;

    for (int kc = 0; kc < 4; kc++) {
        __syncthreads();
        for (int m = tid; m < 64*MID_/4; m += 256) {
            int rr = m >> 5, cg = (m & 31) * 4;
            *(float4*)&Wts[rr*MID_ + cg] = *(const float4*)&W[(size_t)(kc*64 + rr)*MID_ + cg];
        }
        __syncthreads();
        #pragma unroll 16
        for (int k = 0; k < 64; k++) {
            float a = zs[r*Z_ + kc*64 + k];
            float4 w0 = *(const float4*)&Wts[k*MID_ + c0];
            float4 w1 = *(const float4*)&Wts[k*MID_ + c0 + 4];
            acc[0] += a*w0.x; acc[1] += a*w0.y; acc[2] += a*w0.z; acc[3] += a*w0.w;
            acc[4] += a*w1.x; acc[5] += a*w1.y; acc[6] += a*w1.z; acc[7] += a*w1.w;
        }
    }

    #pragma unroll
    for (int c = 0; c < 8; c++) {
        float extra = bias[c0 + c];
        if (ws == 0) extra += g_msgg[b*MID_ + c0 + c];
        else if (ws == 1) extra += be[c0 + c];
        outp[((size_t)b*N_ + nbase + r)*MID_ + c0 + c] = acc[c] + extra;
    }
}

// ---------------- edge: mma.sync GEMM + masked running max ----------------
__device__ __forceinline__ void mma16816(float d[4], const u32 a[4], const u32 b[2]) {
    asm volatile(
        "mma.sync.aligned.m16n8k16.row.col.f32.f16.f16.f32 "
        "{%0,%1,%2,%3}, {%4,%5,%6,%7}, {%8,%9}, {%0,%1,%2,%3};\n"
        : "+f"(d[0]), "+f"(d[1]), "+f"(d[2]), "+f"(d[3])
        : "r"(a[0]), "r"(a[1]), "r"(a[2]), "r"(a[3]), "r"(b[0]), "r"(b[1]));
}
__device__ __forceinline__ void ldsm4(u32 a[4], u32 addr) {
    asm volatile("ldmatrix.sync.aligned.m8n8.x4.shared.b16 {%0,%1,%2,%3}, [%4];"
                 : "=r"(a[0]), "=r"(a[1]), "=r"(a[2]), "=r"(a[3]) : "r"(addr));
}
__device__ __forceinline__ u32 smem_u32(const void* p) {
    u32 a;
    asm("{ .reg .u64 t; cvta.to.shared.u64 t, %1; cvt.u32.u64 %0, t; }" : "=r"(a) : "l"(p));
    return a;
}

// store a TJ x 128 fp32 slab (8 float4/thread) into fp16 smem buffer
__device__ __forceinline__ void store_slab(__half* As, int tid, const float4 pf[8]) {
    #pragma unroll
    for (int l = 0; l < 8; l++) {
        int m = l*256 + tid, row = m >> 5, c4 = (m & 31) * 4;
        __half2 h0 = __floats2half2_rn(pf[l].x, pf[l].y);
        __half2 h1 = __floats2half2_rn(pf[l].z, pf[l].w);
        uint2 u; u.x = *(u32*)&h0; u.y = *(u32*)&h1;
        *(uint2*)&As[row*PADH + c4] = u;
    }
}
__device__ __forceinline__ void load_slab(float4 pf[8], const float* __restrict__ edge,
                                          int b, int i, int jbase, int tid) {
    const float4* eb = (const float4*)(edge + (((size_t)b*N_ + i)*N_ + jbase)*F_);
    #pragma unroll
    for (int l = 0; l < 8; l++) pf[l] = eb[l*256 + tid];
}

// grid (ICH, N_/TJ, B_) = (32, 8, 2) = 512 CTAs. block 256 = 8 warps (2m x 4n of 32x32).
__global__ __launch_bounds__(256, 1) void edge_kernel(
    const float* __restrict__ edge, const float* __restrict__ adj) {
    __shared__ __align__(16) __half Asb[2][TJ*PADH];   // 2 x 17408 B
    __shared__ float addvsm[TI*MID_];                  // 8 KB
    __shared__ float adjsm [TI*TJ];                    // 4 KB

    int ic = blockIdx.x, jt = blockIdx.y, b = blockIdx.z;
    int jbase = jt * TJ, ibase = ic * TI;
    int tid = threadIdx.x, w = tid >> 5, lane = tid & 31;
    int g = lane >> 2, t = lane & 3;
    int mrow = (w >> 2) * 32, ncol = (w & 3) * 32;

    // persistent B fragments (We): 64 regs
    u32 Bf[8][4][2];
    #pragma unroll
    for (int ks = 0; ks < 8; ks++)
        #pragma unroll
        for (int nf = 0; nf < 4; nf++) {
            int n0 = ncol + nf*8 + g;
            int kb = ks*16 + 2*t;
            Bf[ks][nf][0] = *(const u32*)&g_WeTh[n0*F_ + kb];
            Bf[ks][nf][1] = *(const u32*)&g_WeTh[n0*F_ + kb + 8];
        }

    // preload addv chunk [TI][128] and adj chunk [TI][TJ]
    #pragma unroll
    for (int l = 0; l < 2; l++) {
        int m = l*256 + tid, it = m >> 5, c4 = (m & 31) * 4;
        *(float4*)&addvsm[it*MID_ + c4] =
            *(const float4*)&g_addv[((size_t)b*N_ + ibase + it)*MID_ + c4];
    }
    {
        int it = tid >> 4, r4 = (tid & 15) * 4;
        *(float4*)&adjsm[it*TJ + r4] =
            *(const float4*)&adj[((size_t)b*N_ + ibase + it)*N_ + jbase + r4];
    }

    float maxacc[2][4][4];
    #pragma unroll
    for (int mf = 0; mf < 2; mf++)
        #pragma unroll
        for (int nf = 0; nf < 4; nf++)
            #pragma unroll
            for (int e = 0; e < 4; e++) maxacc[mf][nf][e] = -1e30f;

    // prologue: slab0 -> buf0; pf <- slab1
    float4 pf[8];
    load_slab(pf, edge, b, ibase, jbase, tid);
    store_slab(Asb[0], tid, pf);
    if (TI > 1) load_slab(pf, edge, b, ibase + 1, jbase, tid);
    __syncthreads();

    // per-lane LDSM base addresses (byte offsets into a buffer)
    u32 asb0 = smem_u32(Asb[0]);
    u32 lrow = (u32)((mrow + (lane & 15)) * PADH + (lane >> 4) * 8) * 2;
    u32 lrow16 = lrow + 16 * PADH * 2;   // +16 rows for mf=1
    const u32 bufstride = TJ * PADH * 2;

    #pragma unroll 1
    for (int it = 0; it < TI; it++) {
        // 1) stage slab(it+1) into the other buffer (its prior readers synced at it-1)
        if (it + 1 < TI) {
            store_slab(Asb[(it + 1) & 1], tid, pf);
            // 2) prefetch slab(it+2)
            if (it + 2 < TI) load_slab(pf, edge, b, ibase + it + 2, jbase, tid);
        }

        // addv / adj for this i from smem
        float avc[4][2], adjc[2][2];
        #pragma unroll
        for (int nf = 0; nf < 4; nf++) {
            avc[nf][0] = addvsm[it*MID_ + ncol + nf*8 + 2*t];
            avc[nf][1] = addvsm[it*MID_ + ncol + nf*8 + 2*t + 1];
        }
        #pragma unroll
        for (int mf = 0; mf < 2; mf++) {
            adjc[mf][0] = adjsm[it*TJ + mrow + mf*16 + g];
            adjc[mf][1] = adjsm[it*TJ + mrow + mf*16 + g + 8];
        }

        // 3) MMA on buf(it&1), acc init = addv
        float d[2][4][4];
        #pragma unroll
        for (int mf = 0; mf < 2; mf++)
            #pragma unroll
            for (int nf = 0; nf < 4; nf++) {
                d[mf][nf][0] = avc[nf][0]; d[mf][nf][1] = avc[nf][1];
                d[mf][nf][2] = avc[nf][0]; d[mf][nf][3] = avc[nf][1];
            }

        u32 abase = asb0 + (u32)(it & 1) * bufstride;
        #pragma unroll
        for (int ks = 0; ks < 8; ks++) {
            u32 a0[4], a1[4];
            ldsm4(a0, abase + lrow   + ks*32);
            ldsm4(a1, abase + lrow16 + ks*32);
            #pragma unroll
            for (int nf = 0; nf < 4; nf++) {
                mma16816(d[0][nf], a0, Bf[ks][nf]);
                mma16816(d[1][nf], a1, Bf[ks][nf]);
            }
        }

        // 4) masked running max over i
        #pragma unroll
        for (int mf = 0; mf < 2; mf++) {
            bool p0 = adjc[mf][0] > 0.f;
            bool p1 = adjc[mf][1] > 0.f;
            #pragma unroll
            for (int nf = 0; nf < 4; nf++) {
                if (p0) {
                    maxacc[mf][nf][0] = fmaxf(maxacc[mf][nf][0], d[mf][nf][0]);
                    maxacc[mf][nf][1] = fmaxf(maxacc[mf][nf][1], d[mf][nf][1]);
                }
                if (p1) {
                    maxacc[mf][nf][2] = fmaxf(maxacc[mf][nf][2], d[mf][nf][2]);
                    maxacc[mf][nf][3] = fmaxf(maxacc[mf][nf][3], d[mf][nf][3]);
                }
            }
        }
        __syncthreads();   // single barrier per iteration
    }

    // stage maxacc in smem (A buffers are dead), coalesced vector store
    float* stage = (float*)Asb;   // 64*128*4 = 32 KB fits in the 34.8 KB A region
    #pragma unroll
    for (int mf = 0; mf < 2; mf++)
        #pragma unroll
        for (int nf = 0; nf < 4; nf++)
            #pragma unroll
            for (int e = 0; e < 4; e++) {
                int jl = mrow + mf*16 + g + (e >> 1)*8;
                int n  = ncol + nf*8 + 2*t + (e & 1);
                stage[jl*MID_ + n] = maxacc[mf][nf][e];
            }
    __syncthreads();
    float4* outp = (float4*)(g_partial + (((size_t)b*ICH + ic)*N_ + jbase)*MID_);
    const float4* st4 = (const float4*)stage;
    #pragma unroll
    for (int l = 0; l < 8; l++) outp[l*256 + tid] = st4[l*256 + tid];
}

// ---------------- combine: chunk-max + base, @Wo2 + bo2 + h1, relu ----------------
// grid 128 (jt 0..63, b 0..1), block 256, 8 j-rows per CTA. Static smem only.
__global__ __launch_bounds__(256) void combine_kernel(
    const float* __restrict__ Wo2, const float* __restrict__ bo2,
    float* __restrict__ out) {
    __shared__ float reds[8*MID_];    // 4 KB
    __shared__ float Wsm [64*MID_];   // 32 KB
    int jt = blockIdx.x & 63, b = blockIdx.x >> 6;
    int jbase = jt * 8;
    int tid = threadIdx.x;
    int r = tid >> 5, c0 = (tid & 31) * 4;

    float4 mx = make_float4(-1e30f, -1e30f, -1e30f, -1e30f);
    #pragma unroll
    for (int icc = 0; icc < ICH; icc++) {   // 32 independent loads in flight
        float4 v = *(const float4*)&g_partial[(((size_t)b*ICH + icc)*N_ + jbase + r)*MID_ + c0];
        mx.x = fmaxf(mx.x, v.x); mx.y = fmaxf(mx.y, v.y);
        mx.z = fmaxf(mx.z, v.z); mx.w = fmaxf(mx.w, v.w);
    }
    float4 bs = *(const float4*)&g_base[((size_t)b*N_ + jbase + r)*MID_ + c0];
    mx.x += bs.x; mx.y += bs.y; mx.z += bs.z; mx.w += bs.w;
    *(float4*)&reds[r*MID_ + c0] = mx;

    float4 acc = make_float4(0.f, 0.f, 0.f, 0.f);
    #pragma unroll
    for (int ph = 0; ph < 2; ph++) {
        __syncthreads();
        #pragma unroll
        for (int l = 0; l < 8; l++) {            // 64 rows of Wo2 per phase
            int m = l*256 + tid;
            ((float4*)Wsm)[m] = ((const float4*)Wo2)[ph*2048 + m];
        }
        __syncthreads();
        #pragma unroll 8
        for (int k = 0; k < 64; k++) {
            float a = reds[r*MID_ + ph*64 + k];
            float4 wv = *(const float4*)&Wsm[k*MID_ + c0];
            acc.x += a*wv.x; acc.y += a*wv.y; acc.z += a*wv.z; acc.w += a*wv.w;
        }
    }

    float4 bo = *(const float4*)&bo2[c0];
    float4 h1 = *(const float4*)&g_h1[((size_t)b*N_ + jbase + r)*MID_ + c0];
    float4 o;
    o.x = fmaxf(acc.x + bo.x + h1.x, 0.f);
    o.y = fmaxf(acc.y + bo.y + h1.y, 0.f);
    o.z = fmaxf(acc.z + bo.z + h1.z, 0.f);
    o.w = fmaxf(acc.w + bo.w + h1.w, 0.f);
    *(float4*)&out[((size_t)b*N_ + jbase + r)*MID_ + c0] = o;
}

// ---------------- launch ----------------
extern "C" void kernel_launch(void* const* d_in, const int* in_sizes, int n_in,
                              void* d_out, int out_size) {
    const float* node   = (const float*)d_in[0];
    const float* edge   = (const float*)d_in[1];
    const float* graph  = (const float*)d_in[2];
    const float* adj    = (const float*)d_in[3];
    const float* hidden = (const float*)d_in[4];
    const float* W1  = (const float*)d_in[5];
    const float* b1  = (const float*)d_in[6];
    const float* W2  = (const float*)d_in[7];
    const float* b2  = (const float*)d_in[8];
    const float* We  = (const float*)d_in[9];
    const float* be  = (const float*)d_in[10];
    const float* Wg  = (const float*)d_in[11];
    const float* bg  = (const float*)d_in[12];
    const float* Wo1 = (const float*)d_in[13];
    const float* bo1 = (const float*)d_in[14];
    const float* Wo2 = (const float*)d_in[15];
    const float* bo2 = (const float*)d_in[16];

    prep_kernel<<<1, 256>>>(graph, Wg, bg, We);
    stageA_kernel<<<dim3(3, 32, 2), 256>>>(node, hidden, W1, b1, W2, b2, Wo1, bo1, be);
    edge_kernel<<<dim3(ICH, N_/TJ, B_), 256>>>(edge, adj);
    combine_kernel<<<128, 256>>>(Wo2, bo2, (float*)d_out);
}